// round 3
// baseline (speedup 1.0000x reference)
#include <cuda_runtime.h>

// VQC simulator: NQ=10 qubits, NL=4 layers, B=2048 batch, C=4 outputs.
// One warp per batch element; 1024-amp state lives in registers:
//   flat index i in [0,1024): qubit q <-> bit (9-q).
//   lane = bits[9:5] (qubits 0..4), local j = bits[4:0] (qubits 5..9).

#define NQ 10
#define NL 4
#define NC 4
#define BATCH 2048

struct Mat {
    float m00r, m00i, m01r, m01i, m10r, m10i, m11r, m11i;
};

// Fused M = Rot * RX.  r[8] = Rot entries, RX = [[c, -i s], [-i s, c]].
__device__ __forceinline__ Mat fuse(const float* __restrict__ r, float c, float s) {
    Mat M;
    M.m00r = r[0] * c + r[3] * s;
    M.m00i = r[1] * c - r[2] * s;
    M.m01r = r[1] * s + r[2] * c;
    M.m01i = r[3] * c - r[0] * s;
    M.m10r = r[4] * c + r[7] * s;
    M.m10i = r[5] * c - r[6] * s;
    M.m11r = r[5] * s + r[6] * c;
    M.m11i = r[7] * c - r[4] * s;
    return M;
}

// 1q gate on a lane bit (qubits 0..4). LM = lane-bit mask.
template <int LM>
__device__ __forceinline__ void gate_lane(float (&ar)[32], float (&ai)[32],
                                          const Mat& M, int lane) {
    const bool hi = (lane & LM) != 0;
    const float car = hi ? M.m11r : M.m00r;
    const float cai = hi ? M.m11i : M.m00i;
    const float cbr = hi ? M.m10r : M.m01r;
    const float cbi = hi ? M.m10i : M.m01i;
#pragma unroll
    for (int j = 0; j < 32; j++) {
        float pr = __shfl_xor_sync(0xffffffffu, ar[j], LM);
        float pi = __shfl_xor_sync(0xffffffffu, ai[j], LM);
        float sr = ar[j], si = ai[j];
        ar[j] = car * sr - cai * si + cbr * pr - cbi * pi;
        ai[j] = car * si + cai * sr + cbr * pi + cbi * pr;
    }
}

// 1q gate on a local bit (qubits 5..9). MT = local-bit mask.
template <int MT>
__device__ __forceinline__ void gate_local(float (&ar)[32], float (&ai)[32],
                                           const Mat& M) {
#pragma unroll
    for (int j = 0; j < 32; j++) {
        if ((j & MT) == 0) {
            const int k = j | MT;
            float a0r = ar[j], a0i = ai[j];
            float a1r = ar[k], a1i = ai[k];
            ar[j] = M.m00r * a0r - M.m00i * a0i + M.m01r * a1r - M.m01i * a1i;
            ai[j] = M.m00r * a0i + M.m00i * a0r + M.m01r * a1i + M.m01i * a1r;
            ar[k] = M.m10r * a0r - M.m10i * a0i + M.m11r * a1r - M.m11i * a1i;
            ai[k] = M.m10r * a0i + M.m10i * a0r + M.m11r * a1i + M.m11i * a1r;
        }
    }
}

// CNOT, control+target both local bits.
template <int CM, int TM>
__device__ __forceinline__ void cnot_ll(float (&ar)[32], float (&ai)[32]) {
#pragma unroll
    for (int j = 0; j < 32; j++) {
        if ((j & CM) != 0 && (j & TM) == 0) {
            const int k = j | TM;
            float t;
            t = ar[j]; ar[j] = ar[k]; ar[k] = t;
            t = ai[j]; ai[j] = ai[k]; ai[k] = t;
        }
    }
}

// Fused lane-bit CNOT chain (0,1)(1,2)(2,3)(3,4) as one lane permutation.
// Source lane s: reverse-order composition, each step flips target if control set.
__device__ __forceinline__ void cnot_lane_chain(float (&ar)[32], float (&ai)[32],
                                                int lane) {
    int s = lane;
    if (s & 2)  s ^= 1;   // CNOT(3,4): lane bits (1 -> 0)
    if (s & 4)  s ^= 2;   // CNOT(2,3): lane bits (2 -> 1)
    if (s & 8)  s ^= 4;   // CNOT(1,2): lane bits (3 -> 2)
    if (s & 16) s ^= 8;   // CNOT(0,1): lane bits (4 -> 3)
#pragma unroll
    for (int j = 0; j < 32; j++) {
        ar[j] = __shfl_sync(0xffffffffu, ar[j], s);
        ai[j] = __shfl_sync(0xffffffffu, ai[j], s);
    }
}

// CNOT(4,5): control = lane bit 0, target = local bit 4 (mask 16).
__device__ __forceinline__ void cnot_45(float (&ar)[32], float (&ai)[32], int lane) {
    if (lane & 1) {
#pragma unroll
        for (int j = 0; j < 16; j++) {
            const int k = j | 16;
            float t;
            t = ar[j]; ar[j] = ar[k]; ar[k] = t;
            t = ai[j]; ai[j] = ai[k]; ai[k] = t;
        }
    }
}

// CNOT(9,0): control = local bit 0, target = lane bit 4 (mask 16).
// All odd-local amps exchange across lane^16 unconditionally.
__device__ __forceinline__ void cnot_90(float (&ar)[32], float (&ai)[32]) {
#pragma unroll
    for (int j = 1; j < 32; j += 2) {
        ar[j] = __shfl_xor_sync(0xffffffffu, ar[j], 16);
        ai[j] = __shfl_xor_sync(0xffffffffu, ai[j], 16);
    }
}

__global__ __launch_bounds__(128, 4)
void vqc_kernel(const float* __restrict__ x, const float* __restrict__ weights,
                const float* __restrict__ bias, const float* __restrict__ osf,
                float* __restrict__ out) {
    __shared__ float srot[NL * NQ * 8];

    const int tid = threadIdx.x;

    // Precompute Rot matrices (batch-independent) once per CTA.
    if (tid < NL * NQ) {
        const float phi = weights[tid * 3 + 0];
        const float th  = weights[tid * 3 + 1];
        const float om  = weights[tid * 3 + 2];
        float ssn, cc;  __sincosf(0.5f * th, &ssn, &cc);
        float sa, ca;   __sincosf(0.5f * (phi + om), &sa, &ca);
        float sb, cb;   __sincosf(0.5f * (phi - om), &sb, &cb);
        float* r = &srot[tid * 8];
        r[0] =  ca * cc;  r[1] = -sa * cc;   // m00
        r[2] = -cb * ssn; r[3] = -sb * ssn;  // m01
        r[4] =  cb * ssn; r[5] = -sb * ssn;  // m10
        r[6] =  ca * cc;  r[7] =  sa * cc;   // m11
    }
    __syncthreads();

    const int warp = tid >> 5;
    const int lane = tid & 31;
    const int b = blockIdx.x * 4 + warp;

    // RX angles: cos/sin(x/2), reused across layers.
    float rxc[NQ], rxs[NQ];
#pragma unroll
    for (int q = 0; q < NQ; q++) {
        __sincosf(0.5f * x[b * NQ + q], &rxs[q], &rxc[q]);
    }

    // State: |0...0>.
    float ar[32], ai[32];
#pragma unroll
    for (int j = 0; j < 32; j++) { ar[j] = 0.0f; ai[j] = 0.0f; }
    if (lane == 0) ar[0] = 1.0f;

#pragma unroll 1
    for (int l = 0; l < NL; l++) {
        const float* rl = &srot[l * NQ * 8];

        // Fused (Rot * RX) gates: qubits 0..4 are lane bits, 5..9 local bits.
        { Mat M = fuse(rl + 0 * 8, rxc[0], rxs[0]); gate_lane<16>(ar, ai, M, lane); }
        { Mat M = fuse(rl + 1 * 8, rxc[1], rxs[1]); gate_lane< 8>(ar, ai, M, lane); }
        { Mat M = fuse(rl + 2 * 8, rxc[2], rxs[2]); gate_lane< 4>(ar, ai, M, lane); }
        { Mat M = fuse(rl + 3 * 8, rxc[3], rxs[3]); gate_lane< 2>(ar, ai, M, lane); }
        { Mat M = fuse(rl + 4 * 8, rxc[4], rxs[4]); gate_lane< 1>(ar, ai, M, lane); }
        { Mat M = fuse(rl + 5 * 8, rxc[5], rxs[5]); gate_local<16>(ar, ai, M); }
        { Mat M = fuse(rl + 6 * 8, rxc[6], rxs[6]); gate_local< 8>(ar, ai, M); }
        { Mat M = fuse(rl + 7 * 8, rxc[7], rxs[7]); gate_local< 4>(ar, ai, M); }
        { Mat M = fuse(rl + 8 * 8, rxc[8], rxs[8]); gate_local< 2>(ar, ai, M); }
        { Mat M = fuse(rl + 9 * 8, rxc[9], rxs[9]); gate_local< 1>(ar, ai, M); }

        // Ring CNOTs in order (0,1)..(8,9),(9,0).
        cnot_lane_chain(ar, ai, lane); // (0,1)(1,2)(2,3)(3,4) fused
        cnot_45(ar, ai, lane);         // (4,5)
        cnot_ll<16, 8>(ar, ai);        // (5,6)
        cnot_ll< 8, 4>(ar, ai);        // (6,7)
        cnot_ll< 4, 2>(ar, ai);        // (7,8)
        cnot_ll< 2, 1>(ar, ai);        // (8,9)
        cnot_90(ar, ai);               // (9,0)
    }

    // Probabilities and Z-expectations for qubits 0..3 (all lane bits).
    float s = 0.0f;
#pragma unroll
    for (int j = 0; j < 32; j++) {
        s = fmaf(ar[j], ar[j], s);
        s = fmaf(ai[j], ai[j], s);
    }

    float z0 = (lane & 16) ? -s : s;  // qubit 0 -> lane bit 4
    float z1 = (lane &  8) ? -s : s;  // qubit 1 -> lane bit 3
    float z2 = (lane &  4) ? -s : s;  // qubit 2 -> lane bit 2
    float z3 = (lane &  2) ? -s : s;  // qubit 3 -> lane bit 1
#pragma unroll
    for (int o = 16; o >= 1; o >>= 1) {
        z0 += __shfl_xor_sync(0xffffffffu, z0, o);
        z1 += __shfl_xor_sync(0xffffffffu, z1, o);
        z2 += __shfl_xor_sync(0xffffffffu, z2, o);
        z3 += __shfl_xor_sync(0xffffffffu, z3, o);
    }

    if (lane == 0) {
        float t0 = (z0 + bias[0]) * osf[0];
        float t1 = (z1 + bias[1]) * osf[1];
        float t2 = (z2 + bias[2]) * osf[2];
        float t3 = (z3 + bias[3]) * osf[3];
        float m = fmaxf(fmaxf(t0, t1), fmaxf(t2, t3));
        float e0 = __expf(t0 - m);
        float e1 = __expf(t1 - m);
        float e2 = __expf(t2 - m);
        float e3 = __expf(t3 - m);
        float inv = 1.0f / (e0 + e1 + e2 + e3);
        float4 o4 = make_float4(e0 * inv, e1 * inv, e2 * inv, e3 * inv);
        reinterpret_cast<float4*>(out)[b] = o4;
    }
}

extern "C" void kernel_launch(void* const* d_in, const int* in_sizes, int n_in,
                              void* d_out, int out_size) {
    const float* x       = (const float*)d_in[0];  // (2048, 10)
    const float* weights = (const float*)d_in[1];  // (4, 10, 3)
    const float* bias    = (const float*)d_in[2];  // (4,)
    const float* osf     = (const float*)d_in[3];  // (4,)
    float* out = (float*)d_out;                    // (2048, 4)

    vqc_kernel<<<BATCH / 4, 128>>>(x, weights, bias, osf, out);
}

// round 5
// speedup vs baseline: 1.2406x; 1.2406x over previous
#include <cuda_runtime.h>

// VQC simulator: NQ=10 qubits, NL=4 layers, B=2048, C=4.
// One warp per batch element; 1024 complex amps in registers, PACKED:
//   flat index i: qubit q <-> bit (9-q). lane = bits[9:5] (qubits 0..4),
//   local j = bits[4:0] (qubits 5..9), j = 2t + h: pack index t in [0,16),
//   half h. R[t] = (re[2t], re[2t+1]) as f32x2; I[t] = imag same.
// 9 of 10 gates/layer use packed fma.rn.f32x2 (2 FMAs/instr).

#define NQ 10
#define NL 4
#define BATCH 2048

typedef unsigned long long ull;

__device__ __forceinline__ ull mul2(ull a, ull b) {
    ull d; asm("mul.rn.f32x2 %0, %1, %2;" : "=l"(d) : "l"(a), "l"(b)); return d;
}
__device__ __forceinline__ ull fma2(ull a, ull b, ull c) {
    ull d; asm("fma.rn.f32x2 %0, %1, %2, %3;" : "=l"(d) : "l"(a), "l"(b), "l"(c)); return d;
}
__device__ __forceinline__ ull pk(float v) {
    ull d; asm("mov.b64 %0, {%1, %1};" : "=l"(d) : "f"(v)); return d;
}
__device__ __forceinline__ ull pack2(float x, float y) {
    ull d; asm("mov.b64 %0, {%1, %2};" : "=l"(d) : "f"(x), "f"(y)); return d;
}
__device__ __forceinline__ float2 unpack2(ull v) {
    float2 r; asm("mov.b64 {%0, %1}, %2;" : "=f"(r.x), "=f"(r.y) : "l"(v)); return r;
}

struct Mat { float m00r, m00i, m01r, m01i, m10r, m10i, m11r, m11i; };

struct MatP {
    ull c00r, c00i, n00i, c01r, c01i, n01i;
    ull c10r, c10i, n10i, c11r, c11i, n11i;
};

__device__ __forceinline__ MatP pack_mat(const Mat& M) {
    MatP P;
    P.c00r = pk(M.m00r); P.c00i = pk(M.m00i); P.n00i = pk(-M.m00i);
    P.c01r = pk(M.m01r); P.c01i = pk(M.m01i); P.n01i = pk(-M.m01i);
    P.c10r = pk(M.m10r); P.c10i = pk(M.m10i); P.n10i = pk(-M.m10i);
    P.c11r = pk(M.m11r); P.c11i = pk(M.m11i); P.n11i = pk(-M.m11i);
    return P;
}

// Fused M = Rot * RX.
__device__ __forceinline__ Mat fuse(const float* __restrict__ r, float c, float s) {
    Mat M;
    M.m00r = r[0] * c + r[3] * s;
    M.m00i = r[1] * c - r[2] * s;
    M.m01r = r[1] * s + r[2] * c;
    M.m01i = r[3] * c - r[0] * s;
    M.m10r = r[4] * c + r[7] * s;
    M.m10i = r[5] * c - r[6] * s;
    M.m11r = r[5] * s + r[6] * c;
    M.m11i = r[7] * c - r[4] * s;
    return M;
}

// 1q gate on a lane bit (qubits 0..4): packed arithmetic, shfl halves.
template <int LM>
__device__ __forceinline__ void gate_lane(ull (&R)[16], ull (&I)[16],
                                          const Mat& M, int lane) {
    const bool hi = (lane & LM) != 0;
    const float car = hi ? M.m11r : M.m00r;
    const float cai = hi ? M.m11i : M.m00i;
    const float cbr = hi ? M.m10r : M.m01r;
    const float cbi = hi ? M.m10i : M.m01i;
    const ull Par = pk(car), Pai = pk(cai), Nai = pk(-cai);
    const ull Pbr = pk(cbr), Pbi = pk(cbi), Nbi = pk(-cbi);
#pragma unroll
    for (int t = 0; t < 16; t++) {
        float2 r = unpack2(R[t]), i = unpack2(I[t]);
        float prx = __shfl_xor_sync(0xffffffffu, r.x, LM);
        float pry = __shfl_xor_sync(0xffffffffu, r.y, LM);
        float pix = __shfl_xor_sync(0xffffffffu, i.x, LM);
        float piy = __shfl_xor_sync(0xffffffffu, i.y, LM);
        ull PR = pack2(prx, pry), PI = pack2(pix, piy);
        ull nr = fma2(Nbi, PI, fma2(Pbr, PR, fma2(Nai, I[t], mul2(Par, R[t]))));
        ull ni = fma2(Pbi, PR, fma2(Pbr, PI, fma2(Pai, R[t], mul2(Par, I[t]))));
        R[t] = nr; I[t] = ni;
    }
}

// 1q gate on local qubits 5..8: pack-bit mask PM = (j-mask)>>1.
template <int PM>
__device__ __forceinline__ void gate_local_p(ull (&R)[16], ull (&I)[16],
                                             const MatP& P) {
#pragma unroll
    for (int t = 0; t < 16; t++) {
        if ((t & PM) == 0) {
            const int u = t | PM;
            ull a0r = R[t], a0i = I[t], a1r = R[u], a1i = I[u];
            R[t] = fma2(P.n01i, a1i, fma2(P.c01r, a1r, fma2(P.n00i, a0i, mul2(P.c00r, a0r))));
            I[t] = fma2(P.c01i, a1r, fma2(P.c01r, a1i, fma2(P.c00i, a0r, mul2(P.c00r, a0i))));
            R[u] = fma2(P.n11i, a1i, fma2(P.c11r, a1r, fma2(P.n10i, a0i, mul2(P.c10r, a0r))));
            I[u] = fma2(P.c11i, a1r, fma2(P.c11r, a1i, fma2(P.c10i, a0r, mul2(P.c10r, a0i))));
        }
    }
}

// 1q gate on qubit 9 (intra-pack halves): scalar.
__device__ __forceinline__ void gate_q9(ull (&R)[16], ull (&I)[16], const Mat& M) {
#pragma unroll
    for (int t = 0; t < 16; t++) {
        float2 r = unpack2(R[t]), i = unpack2(I[t]);
        float n0r = M.m00r * r.x - M.m00i * i.x + M.m01r * r.y - M.m01i * i.y;
        float n0i = M.m00r * i.x + M.m00i * r.x + M.m01r * i.y + M.m01i * r.y;
        float n1r = M.m10r * r.x - M.m10i * i.x + M.m11r * r.y - M.m11i * i.y;
        float n1i = M.m10r * i.x + M.m10i * r.x + M.m11r * i.y + M.m11i * r.y;
        R[t] = pack2(n0r, n1r);
        I[t] = pack2(n0i, n1i);
    }
}

// CNOT pack-swap: swap packs t <-> t|TP where (t & CP) && !(t & TP).
template <int CP, int TP>
__device__ __forceinline__ void cnot_pp(ull (&R)[16], ull (&I)[16]) {
#pragma unroll
    for (int t = 0; t < 16; t++) {
        if ((t & CP) != 0 && (t & TP) == 0) {
            const int u = t | TP;
            ull w;
            w = R[t]; R[t] = R[u]; R[u] = w;
            w = I[t]; I[t] = I[u]; I[u] = w;
        }
    }
}

// Fused lane-bit CNOT chain (0,1)(1,2)(2,3)(3,4): one lane permutation.
__device__ __forceinline__ void cnot_lane_chain(ull (&R)[16], ull (&I)[16],
                                                int lane) {
    int s = lane;
    if (s & 2)  s ^= 1;
    if (s & 4)  s ^= 2;
    if (s & 8)  s ^= 4;
    if (s & 16) s ^= 8;
#pragma unroll
    for (int t = 0; t < 16; t++) {
        float2 r = unpack2(R[t]), i = unpack2(I[t]);
        r.x = __shfl_sync(0xffffffffu, r.x, s);
        r.y = __shfl_sync(0xffffffffu, r.y, s);
        i.x = __shfl_sync(0xffffffffu, i.x, s);
        i.y = __shfl_sync(0xffffffffu, i.y, s);
        R[t] = pack2(r.x, r.y);
        I[t] = pack2(i.x, i.y);
    }
}

// CNOT(4,5): control lane bit0, target pack bit 3.
__device__ __forceinline__ void cnot_45(ull (&R)[16], ull (&I)[16], int lane) {
    if (lane & 1) {
#pragma unroll
        for (int t = 0; t < 8; t++) {
            const int u = t | 8;
            ull w;
            w = R[t]; R[t] = R[u]; R[u] = w;
            w = I[t]; I[t] = I[u]; I[u] = w;
        }
    }
}

// CNOT(8,9): control pack bit0 (j bit1), target intra-pack half.
__device__ __forceinline__ void cnot_89(ull (&R)[16], ull (&I)[16]) {
#pragma unroll
    for (int t = 1; t < 16; t += 2) {
        float2 r = unpack2(R[t]), i = unpack2(I[t]);
        R[t] = pack2(r.y, r.x);
        I[t] = pack2(i.y, i.x);
    }
}

// CNOT(9,0): control j bit0 (hi half), target lane bit 4: shfl hi halves.
__device__ __forceinline__ void cnot_90(ull (&R)[16], ull (&I)[16]) {
#pragma unroll
    for (int t = 0; t < 16; t++) {
        float2 r = unpack2(R[t]), i = unpack2(I[t]);
        r.y = __shfl_xor_sync(0xffffffffu, r.y, 16);
        i.y = __shfl_xor_sync(0xffffffffu, i.y, 16);
        R[t] = pack2(r.x, r.y);
        I[t] = pack2(i.x, i.y);
    }
}

__global__ __launch_bounds__(64, 8)
void vqc_kernel(const float* __restrict__ x, const float* __restrict__ weights,
                const float* __restrict__ bias, const float* __restrict__ osf,
                float* __restrict__ out) {
    __shared__ float srot[NL * NQ * 8];

    const int tid = threadIdx.x;

    // Precompute Rot matrices (batch-independent) once per CTA.
    if (tid < NL * NQ) {
        const float phi = weights[tid * 3 + 0];
        const float th  = weights[tid * 3 + 1];
        const float om  = weights[tid * 3 + 2];
        float ssn, cc;  __sincosf(0.5f * th, &ssn, &cc);
        float sa, ca;   __sincosf(0.5f * (phi + om), &sa, &ca);
        float sb, cb;   __sincosf(0.5f * (phi - om), &sb, &cb);
        float* r = &srot[tid * 8];
        r[0] =  ca * cc;  r[1] = -sa * cc;   // m00
        r[2] = -cb * ssn; r[3] = -sb * ssn;  // m01
        r[4] =  cb * ssn; r[5] = -sb * ssn;  // m10
        r[6] =  ca * cc;  r[7] =  sa * cc;   // m11
    }
    __syncthreads();

    const int warp = tid >> 5;
    const int lane = tid & 31;
    const int b = blockIdx.x * 2 + warp;

    // RX angles: cos/sin(x/2), reused across layers.
    float rxc[NQ], rxs[NQ];
#pragma unroll
    for (int q = 0; q < NQ; q++) {
        __sincosf(0.5f * x[b * NQ + q], &rxs[q], &rxc[q]);
    }

    // State |0...0>.
    ull R[16], I[16];
#pragma unroll
    for (int t = 0; t < 16; t++) { R[t] = 0ull; I[t] = 0ull; }
    if (lane == 0) R[0] = pack2(1.0f, 0.0f);

#pragma unroll 1
    for (int l = 0; l < NL; l++) {
        const float* rl = &srot[l * NQ * 8];

        // Fused (Rot*RX): qubits 0..4 lane bits, 5..8 pack bits, 9 intra-pack.
        { Mat M = fuse(rl + 0 * 8, rxc[0], rxs[0]); gate_lane<16>(R, I, M, lane); }
        { Mat M = fuse(rl + 1 * 8, rxc[1], rxs[1]); gate_lane< 8>(R, I, M, lane); }
        { Mat M = fuse(rl + 2 * 8, rxc[2], rxs[2]); gate_lane< 4>(R, I, M, lane); }
        { Mat M = fuse(rl + 3 * 8, rxc[3], rxs[3]); gate_lane< 2>(R, I, M, lane); }
        { Mat M = fuse(rl + 4 * 8, rxc[4], rxs[4]); gate_lane< 1>(R, I, M, lane); }
        { Mat M = fuse(rl + 5 * 8, rxc[5], rxs[5]); MatP P = pack_mat(M); gate_local_p<8>(R, I, P); }
        { Mat M = fuse(rl + 6 * 8, rxc[6], rxs[6]); MatP P = pack_mat(M); gate_local_p<4>(R, I, P); }
        { Mat M = fuse(rl + 7 * 8, rxc[7], rxs[7]); MatP P = pack_mat(M); gate_local_p<2>(R, I, P); }
        { Mat M = fuse(rl + 8 * 8, rxc[8], rxs[8]); MatP P = pack_mat(M); gate_local_p<1>(R, I, P); }
        { Mat M = fuse(rl + 9 * 8, rxc[9], rxs[9]); gate_q9(R, I, M); }

        // Ring CNOTs (0,1)..(8,9),(9,0).
        cnot_lane_chain(R, I, lane);  // (0,1)(1,2)(2,3)(3,4)
        cnot_45(R, I, lane);          // (4,5)
        cnot_pp<8, 4>(R, I);          // (5,6): j bits 4,3 -> pack bits 3,2
        cnot_pp<4, 2>(R, I);          // (6,7)
        cnot_pp<2, 1>(R, I);          // (7,8)
        cnot_89(R, I);                // (8,9)
        cnot_90(R, I);                // (9,0)
    }

    // Probabilities + Z-expectations for qubits 0..3 (lane bits).
    float s = 0.0f;
#pragma unroll
    for (int t = 0; t < 16; t++) {
        float2 r = unpack2(R[t]), i = unpack2(I[t]);
        s = fmaf(r.x, r.x, s);
        s = fmaf(r.y, r.y, s);
        s = fmaf(i.x, i.x, s);
        s = fmaf(i.y, i.y, s);
    }

    float z0 = (lane & 16) ? -s : s;
    float z1 = (lane &  8) ? -s : s;
    float z2 = (lane &  4) ? -s : s;
    float z3 = (lane &  2) ? -s : s;
#pragma unroll
    for (int o = 16; o >= 1; o >>= 1) {
        z0 += __shfl_xor_sync(0xffffffffu, z0, o);
        z1 += __shfl_xor_sync(0xffffffffu, z1, o);
        z2 += __shfl_xor_sync(0xffffffffu, z2, o);
        z3 += __shfl_xor_sync(0xffffffffu, z3, o);
    }

    if (lane == 0) {
        float t0 = (z0 + bias[0]) * osf[0];
        float t1 = (z1 + bias[1]) * osf[1];
        float t2 = (z2 + bias[2]) * osf[2];
        float t3 = (z3 + bias[3]) * osf[3];
        float m = fmaxf(fmaxf(t0, t1), fmaxf(t2, t3));
        float e0 = __expf(t0 - m);
        float e1 = __expf(t1 - m);
        float e2 = __expf(t2 - m);
        float e3 = __expf(t3 - m);
        float inv = 1.0f / (e0 + e1 + e2 + e3);
        float4 o4 = make_float4(e0 * inv, e1 * inv, e2 * inv, e3 * inv);
        reinterpret_cast<float4*>(out)[b] = o4;
    }
}

extern "C" void kernel_launch(void* const* d_in, const int* in_sizes, int n_in,
                              void* d_out, int out_size) {
    const float* x       = (const float*)d_in[0];  // (2048, 10)
    const float* weights = (const float*)d_in[1];  // (4, 10, 3)
    const float* bias    = (const float*)d_in[2];  // (4,)
    const float* osf     = (const float*)d_in[3];  // (4,)
    float* out = (float*)d_out;                    // (2048, 4)

    vqc_kernel<<<BATCH / 2, 64>>>(x, weights, bias, osf, out);
}

// round 8
// speedup vs baseline: 1.3228x; 1.0662x over previous
#include <cuda_runtime.h>

// VQC simulator: NQ=10, NL=4, B=2048, C=4.
// One warp per batch element; 1024 complex amps in registers, PACKED f32x2:
//   qubit q <-> flat bit (9-q); lane = bits[9:5] (q0..4),
//   pack t = bits[4:1] (q5..8), half = bit0 (q9).
// All gate matrices are SU(2): M = [[a, b], [-conj(b), conj(a)]].

#define NQ 10
#define NL 4
#define BATCH 2048

typedef unsigned long long ull;

__device__ __forceinline__ ull mul2(ull a, ull b) {
    ull d; asm("mul.rn.f32x2 %0, %1, %2;" : "=l"(d) : "l"(a), "l"(b)); return d;
}
__device__ __forceinline__ ull fma2(ull a, ull b, ull c) {
    ull d; asm("fma.rn.f32x2 %0, %1, %2, %3;" : "=l"(d) : "l"(a), "l"(b), "l"(c)); return d;
}
__device__ __forceinline__ ull pk(float v) {
    ull d; asm("mov.b64 %0, {%1, %1};" : "=l"(d) : "f"(v)); return d;
}
__device__ __forceinline__ ull pack2(float x, float y) {
    ull d; asm("mov.b64 %0, {%1, %2};" : "=l"(d) : "f"(x), "f"(y)); return d;
}
__device__ __forceinline__ float2 unpack2(ull v) {
    float2 r; asm("mov.b64 {%0, %1}, %2;" : "=f"(r.x), "=f"(r.y) : "l"(v)); return r;
}

// SU(2) gate: (a, b) complex. Fused M = Rot * RX from Rot's top row (r0..r3)
// and RX cos/sin: a = m00, b = m01.
struct Gate { float ar, ai, br, bi; };

__device__ __forceinline__ Gate fuse(float4 r, float c, float s) {
    Gate G;
    G.ar = r.x * c + r.w * s;
    G.ai = r.y * c - r.z * s;
    G.br = r.y * s + r.z * c;
    G.bi = r.w * c - r.x * s;
    return G;
}

// 1q gate on a lane bit (q0..4): packed arithmetic, shfl halves.
//   lo lanes: out = a*x + b*p ; hi lanes: out = conj(a)*x - conj(b)*p.
template <int LM>
__device__ __forceinline__ void gate_lane(ull (&R)[16], ull (&I)[16],
                                          const Gate& G, int lane) {
    const bool hi = (lane & LM) != 0;
    const float cai = hi ? -G.ai : G.ai;
    const float cbr = hi ? -G.br : G.br;
    const ull Par = pk(G.ar), Pai = pk(cai), Nai = pk(-cai);
    const ull Pbr = pk(cbr), Pbi = pk(G.bi), Nbi = pk(-G.bi);
#pragma unroll
    for (int t = 0; t < 16; t++) {
        float2 r = unpack2(R[t]), i = unpack2(I[t]);
        float prx = __shfl_xor_sync(0xffffffffu, r.x, LM);
        float pry = __shfl_xor_sync(0xffffffffu, r.y, LM);
        float pix = __shfl_xor_sync(0xffffffffu, i.x, LM);
        float piy = __shfl_xor_sync(0xffffffffu, i.y, LM);
        ull PR = pack2(prx, pry), PI = pack2(pix, piy);
        ull nr = fma2(Nbi, PI, fma2(Pbr, PR, fma2(Nai, I[t], mul2(Par, R[t]))));
        ull ni = fma2(Pbi, PR, fma2(Pbr, PI, fma2(Pai, R[t], mul2(Par, I[t]))));
        R[t] = nr; I[t] = ni;
    }
}

// 1q gate on pack bits (q5..8): 7 packed SU(2) constants.
template <int PM>
__device__ __forceinline__ void gate_local_p(ull (&R)[16], ull (&I)[16],
                                             const Gate& G) {
    const ull Par = pk(G.ar), Pai = pk(G.ai), Nai = pk(-G.ai);
    const ull Pbr = pk(G.br), Nbr = pk(-G.br), Pbi = pk(G.bi), Nbi = pk(-G.bi);
#pragma unroll
    for (int t = 0; t < 16; t++) {
        if ((t & PM) == 0) {
            const int u = t | PM;
            ull a0r = R[t], a0i = I[t], a1r = R[u], a1i = I[u];
            // out0 = a*x0 + b*x1 ; out1 = -conj(b)*x0 + conj(a)*x1
            R[t] = fma2(Nbi, a1i, fma2(Pbr, a1r, fma2(Nai, a0i, mul2(Par, a0r))));
            I[t] = fma2(Pbi, a1r, fma2(Pbr, a1i, fma2(Pai, a0r, mul2(Par, a0i))));
            R[u] = fma2(Pai, a1i, fma2(Par, a1r, fma2(Nbi, a0i, mul2(Nbr, a0r))));
            I[u] = fma2(Nai, a1r, fma2(Par, a1i, fma2(Pbi, a0r, mul2(Nbr, a0i))));
        }
    }
}

// 1q gate on qubit 9 (intra-pack halves): scalar SU(2).
__device__ __forceinline__ void gate_q9(ull (&R)[16], ull (&I)[16], const Gate& G) {
#pragma unroll
    for (int t = 0; t < 16; t++) {
        float2 r = unpack2(R[t]), i = unpack2(I[t]);
        float n0r = G.ar * r.x - G.ai * i.x + G.br * r.y - G.bi * i.y;
        float n0i = G.ar * i.x + G.ai * r.x + G.br * i.y + G.bi * r.y;
        float n1r = -G.br * r.x - G.bi * i.x + G.ar * r.y + G.ai * i.y;
        float n1i = -G.br * i.x + G.bi * r.x + G.ar * i.y - G.ai * r.y;
        R[t] = pack2(n0r, n1r);
        I[t] = pack2(n0i, n1i);
    }
}

// CNOT pack-swap: swap packs t <-> t|TP where (t & CP) && !(t & TP).
template <int CP, int TP>
__device__ __forceinline__ void cnot_pp(ull (&R)[16], ull (&I)[16]) {
#pragma unroll
    for (int t = 0; t < 16; t++) {
        if ((t & CP) != 0 && (t & TP) == 0) {
            const int u = t | TP;
            ull w;
            w = R[t]; R[t] = R[u]; R[u] = w;
            w = I[t]; I[t] = I[u]; I[u] = w;
        }
    }
}

// Fused lane-bit CNOT chain (0,1)(1,2)(2,3)(3,4): one lane permutation.
__device__ __forceinline__ void cnot_lane_chain(ull (&R)[16], ull (&I)[16],
                                                int lane) {
    int s = lane;
    if (s & 2)  s ^= 1;
    if (s & 4)  s ^= 2;
    if (s & 8)  s ^= 4;
    if (s & 16) s ^= 8;
#pragma unroll
    for (int t = 0; t < 16; t++) {
        float2 r = unpack2(R[t]), i = unpack2(I[t]);
        r.x = __shfl_sync(0xffffffffu, r.x, s);
        r.y = __shfl_sync(0xffffffffu, r.y, s);
        i.x = __shfl_sync(0xffffffffu, i.x, s);
        i.y = __shfl_sync(0xffffffffu, i.y, s);
        R[t] = pack2(r.x, r.y);
        I[t] = pack2(i.x, i.y);
    }
}

// CNOT(4,5): control lane bit0, target pack bit 3.
__device__ __forceinline__ void cnot_45(ull (&R)[16], ull (&I)[16], int lane) {
    if (lane & 1) {
#pragma unroll
        for (int t = 0; t < 8; t++) {
            const int u = t | 8;
            ull w;
            w = R[t]; R[t] = R[u]; R[u] = w;
            w = I[t]; I[t] = I[u]; I[u] = w;
        }
    }
}

// CNOT(8,9): control pack bit0, target intra-pack half.
__device__ __forceinline__ void cnot_89(ull (&R)[16], ull (&I)[16]) {
#pragma unroll
    for (int t = 1; t < 16; t += 2) {
        float2 r = unpack2(R[t]), i = unpack2(I[t]);
        R[t] = pack2(r.y, r.x);
        I[t] = pack2(i.y, i.x);
    }
}

// CNOT(9,0): control hi half, target lane bit 4: shfl hi halves.
__device__ __forceinline__ void cnot_90(ull (&R)[16], ull (&I)[16]) {
#pragma unroll
    for (int t = 0; t < 16; t++) {
        float2 r = unpack2(R[t]), i = unpack2(I[t]);
        r.y = __shfl_xor_sync(0xffffffffu, r.y, 16);
        i.y = __shfl_xor_sync(0xffffffffu, i.y, 16);
        R[t] = pack2(r.x, r.y);
        I[t] = pack2(i.x, i.y);
    }
}

__global__ __launch_bounds__(32, 16)
void vqc_kernel(const float* __restrict__ x, const float* __restrict__ weights,
                const float* __restrict__ bias, const float* __restrict__ osf,
                float* __restrict__ out) {
    // Rot top-row only (SU(2)): 4 floats per gate, float4-aligned.
    __shared__ float4 srot[NL * NQ];

    const int lane = threadIdx.x;
    const int b = blockIdx.x;

    // Precompute Rot matrices (batch-independent) once per CTA.
    for (int g = lane; g < NL * NQ; g += 32) {
        const float phi = weights[g * 3 + 0];
        const float th  = weights[g * 3 + 1];
        const float om  = weights[g * 3 + 2];
        float ssn, cc;  __sincosf(0.5f * th, &ssn, &cc);
        float sa, ca;   __sincosf(0.5f * (phi + om), &sa, &ca);
        float sb, cb;   __sincosf(0.5f * (phi - om), &sb, &cb);
        srot[g] = make_float4(ca * cc, -sa * cc, -cb * ssn, -sb * ssn);
    }
    __syncthreads();

    // RX angles: cos/sin(x/2), reused across layers.
    float rxc[NQ], rxs[NQ];
#pragma unroll
    for (int q = 0; q < NQ; q++) {
        __sincosf(0.5f * x[b * NQ + q], &rxs[q], &rxc[q]);
    }

    // State |0...0>.
    ull R[16], I[16];
#pragma unroll
    for (int t = 0; t < 16; t++) { R[t] = 0ull; I[t] = 0ull; }
    if (lane == 0) R[0] = pack2(1.0f, 0.0f);

#pragma unroll 1
    for (int l = 0; l < NL; l++) {
        const float4* rl = &srot[l * NQ];

        // Fused (Rot*RX): q0..4 lane bits, q5..8 pack bits, q9 intra-pack.
        { Gate G = fuse(rl[0], rxc[0], rxs[0]); gate_lane<16>(R, I, G, lane); }
        { Gate G = fuse(rl[1], rxc[1], rxs[1]); gate_lane< 8>(R, I, G, lane); }
        { Gate G = fuse(rl[2], rxc[2], rxs[2]); gate_lane< 4>(R, I, G, lane); }
        { Gate G = fuse(rl[3], rxc[3], rxs[3]); gate_lane< 2>(R, I, G, lane); }
        { Gate G = fuse(rl[4], rxc[4], rxs[4]); gate_lane< 1>(R, I, G, lane); }
        { Gate G = fuse(rl[5], rxc[5], rxs[5]); gate_local_p<8>(R, I, G); }
        { Gate G = fuse(rl[6], rxc[6], rxs[6]); gate_local_p<4>(R, I, G); }
        { Gate G = fuse(rl[7], rxc[7], rxs[7]); gate_local_p<2>(R, I, G); }
        { Gate G = fuse(rl[8], rxc[8], rxs[8]); gate_local_p<1>(R, I, G); }
        { Gate G = fuse(rl[9], rxc[9], rxs[9]); gate_q9(R, I, G); }

        // Ring CNOTs (0,1)..(8,9),(9,0).
        cnot_lane_chain(R, I, lane);  // (0,1)(1,2)(2,3)(3,4)
        cnot_45(R, I, lane);          // (4,5)
        cnot_pp<8, 4>(R, I);          // (5,6)
        cnot_pp<4, 2>(R, I);          // (6,7)
        cnot_pp<2, 1>(R, I);          // (7,8)
        cnot_89(R, I);                // (8,9)
        cnot_90(R, I);                // (9,0)
    }

    // Probabilities + Z-expectations for qubits 0..3 (lane bits).
    float s = 0.0f;
#pragma unroll
    for (int t = 0; t < 16; t++) {
        float2 r = unpack2(R[t]), i = unpack2(I[t]);
        s = fmaf(r.x, r.x, s);
        s = fmaf(r.y, r.y, s);
        s = fmaf(i.x, i.x, s);
        s = fmaf(i.y, i.y, s);
    }

    float z0 = (lane & 16) ? -s : s;
    float z1 = (lane &  8) ? -s : s;
    float z2 = (lane &  4) ? -s : s;
    float z3 = (lane &  2) ? -s : s;
#pragma unroll
    for (int o = 16; o >= 1; o >>= 1) {
        z0 += __shfl_xor_sync(0xffffffffu, z0, o);
        z1 += __shfl_xor_sync(0xffffffffu, z1, o);
        z2 += __shfl_xor_sync(0xffffffffu, z2, o);
        z3 += __shfl_xor_sync(0xffffffffu, z3, o);
    }

    if (lane == 0) {
        float t0 = (z0 + bias[0]) * osf[0];
        float t1 = (z1 + bias[1]) * osf[1];
        float t2 = (z2 + bias[2]) * osf[2];
        float t3 = (z3 + bias[3]) * osf[3];
        float m = fmaxf(fmaxf(t0, t1), fmaxf(t2, t3));
        float e0 = __expf(t0 - m);
        float e1 = __expf(t1 - m);
        float e2 = __expf(t2 - m);
        float e3 = __expf(t3 - m);
        float inv = 1.0f / (e0 + e1 + e2 + e3);
        float4 o4 = make_float4(e0 * inv, e1 * inv, e2 * inv, e3 * inv);
        reinterpret_cast<float4*>(out)[b] = o4;
    }
}

extern "C" void kernel_launch(void* const* d_in, const int* in_sizes, int n_in,
                              void* d_out, int out_size) {
    const float* x       = (const float*)d_in[0];  // (2048, 10)
    const float* weights = (const float*)d_in[1];  // (4, 10, 3)
    const float* bias    = (const float*)d_in[2];  // (4,)
    const float* osf     = (const float*)d_in[3];  // (4,)
    float* out = (float*)d_out;                    // (2048, 4)

    vqc_kernel<<<BATCH, 32>>>(x, weights, bias, osf, out);
}